// round 5
// baseline (speedup 1.0000x reference)
#include <cuda_runtime.h>
#include <cuda_bf16.h>

// CRF negative log-likelihood, fixed shapes.
#define B_ 256
#define S_ 1024
#define T_ 64
#define PF 8      // emission prefetch ring depth; renorm every 4 steps
#define HPAD 36   // half-vector stride in floats (32 data + 4 pad -> 144B, kills bank conflict)

__device__ float g_diff[B_];

// Packed f32x2 FMA (Blackwell): d = a*b + c elementwise on two packed floats.
__device__ __forceinline__ void fma2(unsigned long long& d,
                                     unsigned long long a,
                                     unsigned long long b,
                                     unsigned long long c) {
    asm("fma.rn.f32x2 %0, %1, %2, %3;" : "=l"(d) : "l"(a), "l"(b), "l"(c));
}
__device__ __forceinline__ unsigned long long pack2(float x, float y) {
    unsigned long long p;
    asm("mov.b64 %0, {%1, %2};" : "=l"(p) : "f"(x), "f"(y));
    return p;
}
__device__ __forceinline__ float2 unpack2(unsigned long long p) {
    float x, y;
    asm("mov.b64 {%0, %1}, %2;" : "=f"(x), "=f"(y) : "l"(p));
    return make_float2(x, y);
}

// 256 threads: bat = tid>>7 (2 batches/block), r = tid&127, tag = r>>1, half = r&1.
// Warps 0-3 -> batch 0, warps 4-7 -> batch 1: each SMSP holds one warp of each
// batch (independent dependency chains -> latency hiding).
__global__ void __launch_bounds__(256) crf_forward_kernel(
    const float* __restrict__ emissions,   // (B, S, T)
    const int* __restrict__ tags,          // (B, S) int32
    const float* __restrict__ trans,       // (T, T)
    const float* __restrict__ startT,      // (T,)
    const float* __restrict__ endT)        // (T,)
{
    const int tid  = threadIdx.x;
    const int bat  = tid >> 7;
    const int r    = tid & 127;
    const int tag  = r >> 1;
    const int half = r & 1;
    const int b    = 2 * blockIdx.x + bat;

    __shared__ __align__(16) float u[2][2][2][HPAD];  // [buf][bat][half][HPAD]
    __shared__ float redA[2][T_];
    __shared__ float redB[2][128];

    // Packed half-column of E = exp(trans): rows [half*32, half*32+32) for this tag.
    unsigned long long e2[16];
#pragma unroll
    for (int k = 0; k < 16; ++k) {
        float lo = __expf(__ldg(trans + (half * 32 + 2 * k + 0) * T_ + tag));
        float hi = __expf(__ldg(trans + (half * 32 + 2 * k + 1) * T_ + tag));
        e2[k] = pack2(lo, hi);
    }

    const float* emb = emissions + (size_t)b * S_ * T_ + tag;

    // t = 0: u0 = exp(start + em0)
    float v = __expf(__ldg(startT + tag) + __ldg(emb));
    if (half == 0) u[0][bat][tag >> 5][tag & 31] = v;
    double c = 0.0;   // running log-scale (r==0 thread of each batch)

    // Prefetch ring: pre-exponentiated emissions (em[t][tag] for t = 1..PF)
    float pf[PF];
#pragma unroll
    for (int k = 0; k < PF; ++k)
        pf[k] = __expf(__ldg(emb + (size_t)(1 + k) * T_));

    __syncthreads();

    int cur = 0;
    int t = 1;

#pragma unroll 1
    for (int tb = 0; tb < 127; ++tb) {
#pragma unroll
        for (int k = 0; k < 8; ++k, ++t) {
            float scale_mul = pf[k];
            if (t + PF < S_)
                pf[k] = __expf(__ldg(emb + (size_t)(t + PF) * T_));

            const float* ub = u[cur][bat][half];

            if ((k & 3) == 0) {
                float scale = u[cur][bat][0][0];       // broadcast LDS
                if (r == 0) c += (double)__logf(scale);
                scale_mul *= __frcp_rn(scale);
            }

            // Half-dot: 32 FMAs as 16 packed FFMA2 (2 independent chains of 8).
            unsigned long long a01 = 0ull, a23 = 0ull;
            const ulonglong2* u8 = reinterpret_cast<const ulonglong2*>(ub);
#pragma unroll
            for (int i = 0; i < 8; ++i) {
                ulonglong2 uu = u8[i];
                fma2(a01, uu.x, e2[2 * i + 0], a01);
                fma2(a23, uu.y, e2[2 * i + 1], a23);
            }
            float2 f01 = unpack2(a01);
            float2 f23 = unpack2(a23);
            float s = (f01.x + f01.y) + (f23.x + f23.y);
            s += __shfl_xor_sync(0xffffffffu, s, 1);   // combine halves
            v = s * scale_mul;

            cur ^= 1;
            if (half == 0) u[cur][bat][tag >> 5][tag & 31] = v;
            __syncthreads();
        }
    }
    // remainder: t = 1017..1023 (7 steps)
#pragma unroll
    for (int k = 0; k < 7; ++k, ++t) {
        float scale_mul = pf[k];
        const float* ub = u[cur][bat][half];

        if ((k & 3) == 0) {
            float scale = u[cur][bat][0][0];
            if (r == 0) c += (double)__logf(scale);
            scale_mul *= __frcp_rn(scale);
        }

        unsigned long long a01 = 0ull, a23 = 0ull;
        const ulonglong2* u8 = reinterpret_cast<const ulonglong2*>(ub);
#pragma unroll
        for (int i = 0; i < 8; ++i) {
            ulonglong2 uu = u8[i];
            fma2(a01, uu.x, e2[2 * i + 0], a01);
            fma2(a23, uu.y, e2[2 * i + 1], a23);
        }
        float2 f01 = unpack2(a01);
        float2 f23 = unpack2(a23);
        float s = (f01.x + f01.y) + (f23.x + f23.y);
        s += __shfl_xor_sync(0xffffffffu, s, 1);
        v = s * scale_mul;

        cur ^= 1;
        if (half == 0) u[cur][bat][tag >> 5][tag & 31] = v;
        __syncthreads();
    }

    // partition = c + log(sum_tag v_tag * exp(end_tag))
    if (half == 0) redA[bat][tag] = v * __expf(__ldg(endT + tag));

    // Gold-path score, 128 threads per batch over time steps.
    float sc = 0.f;
    const int* tg = tags + (size_t)b * S_;
    const float* emB = emissions + (size_t)b * S_ * T_;
#pragma unroll 2
    for (int tt = r; tt < S_; tt += 128) {
        int tg0 = tg[tt];
        sc += __ldg(emB + (size_t)tt * T_ + tg0);
        if (tt + 1 < S_) {
            int tg1 = tg[tt + 1];
            sc += __ldg(trans + tg0 * T_ + tg1);
        }
    }
    if (r == 0) {
        sc += __ldg(startT + tg[0]);
        sc += __ldg(endT + tg[S_ - 1]);
    }
    redB[bat][r] = sc;
    __syncthreads();

    if (r == 0) {
        float sumw = 0.f;
#pragma unroll
        for (int i = 0; i < T_; ++i) sumw += redA[bat][i];
        float sums = 0.f;
#pragma unroll
        for (int i = 0; i < 128; ++i) sums += redB[bat][i];
        double partition = c + (double)__logf(sumw);
        g_diff[b] = (float)(partition - (double)sums);
    }
}

__global__ void crf_reduce_kernel(float* __restrict__ out)
{
    __shared__ float sh[B_];
    int t = threadIdx.x;
    sh[t] = g_diff[t];
    __syncthreads();
#pragma unroll
    for (int off = B_ / 2; off > 0; off >>= 1) {
        if (t < off) sh[t] += sh[t + off];
        __syncthreads();
    }
    if (t == 0) out[0] = sh[0] / (float)B_;
}

extern "C" void kernel_launch(void* const* d_in, const int* in_sizes, int n_in,
                              void* d_out, int out_size)
{
    const float* emissions = (const float*)d_in[0];
    const int*   tags      = (const int*)d_in[1];
    const float* trans     = (const float*)d_in[2];
    const float* startT    = (const float*)d_in[3];
    const float* endT      = (const float*)d_in[4];
    float* out = (float*)d_out;

    crf_forward_kernel<<<B_ / 2, 256>>>(emissions, tags, trans, startT, endT);
    crf_reduce_kernel<<<1, B_>>>(out);
}